// round 5
// baseline (speedup 1.0000x reference)
#include <cuda_runtime.h>
#include <cuda_fp16.h>

// ---------------------------------------------------------------------------
// Problem constants
// ---------------------------------------------------------------------------
#define Dd 8
#define Hh 24
#define Ww 24
#define NV (Dd * Hh * Ww)     /* 4608 voxels */
#define DIMC 192
#define QPS (2 * NV)          /* queries per scale: 2 heads * 4608 = 9216 */
#define PART_STRIDE 36        /* floats per partial record: 32 acc + l + pad */
#define PART_UNIT (QPS * PART_STRIDE)
#define SCALE_F 0.17677669529663687f  /* 32^-0.5 */

static __device__ __align__(16) float  g_q[6 * NV * 32];         // 3.5 MB packed fp32 Q
static __device__ __align__(16) __half g_kh[6 * NV * 32];        // 1.7 MB packed K fp16 (pre-scaled)
static __device__ __align__(16) __half g_vh[6 * NV * 32];        // 1.7 MB packed V fp16
static __device__ __align__(16) float  g_y[NV * DIMC];           // 3.5 MB
static __device__ __align__(16) float  g_part[6 * PART_UNIT];    // 8.0 MB partials

__device__ __forceinline__ int iclamp(int v, int lo, int hi) {
    v = v < lo ? lo : v;
    return v > hi ? hi : v;
}

// ---------------------------------------------------------------------------
// Packed f32x2 helpers (FFMA2 path — 2x FFMA throughput on sm_103a)
// ---------------------------------------------------------------------------
__device__ __forceinline__ unsigned long long pack2(float x, float y) {
    unsigned long long r;
    asm("mov.b64 %0, {%1, %2};" : "=l"(r) : "f"(x), "f"(y));
    return r;
}
__device__ __forceinline__ float2 unpack2(unsigned long long u) {
    float2 r;
    asm("mov.b64 {%0, %1}, %2;" : "=f"(r.x), "=f"(r.y) : "l"(u));
    return r;
}
__device__ __forceinline__ unsigned long long ffma2(
    unsigned long long a, unsigned long long b, unsigned long long c) {
    unsigned long long d;
    asm("fma.rn.f32x2 %0, %1, %2, %3;" : "=l"(d) : "l"(a), "l"(b), "l"(c));
    return d;
}

// ---------------------------------------------------------------------------
// GEMM: C[M,N] = A[M,K] @ B[K,N] + bias[N]
// BM=64, BN=64, BK=16, 256 threads, 4x4 register tile (FFMA2, m-paired).
// Small tile -> many blocks (GEMM1: 648, GEMM2: 216) -> real occupancy.
// PACK=true: scatter q (fp32 packed [hg][vox][32]), k(*SCALE)/v to fp16.
// ---------------------------------------------------------------------------
template <bool PACK>
__global__ __launch_bounds__(256) void gemm_bias_kernel(
    const float* __restrict__ A, const float* __restrict__ B,
    const float* __restrict__ bias, float* __restrict__ C,
    float* __restrict__ gq, __half* __restrict__ gkh, __half* __restrict__ gvh,
    int M, int N, int Kd)
{
    __shared__ float As[16][68];   // 68*4 = 272B row stride (16B multiple)
    __shared__ float Bs[16][64];

    const int tid = threadIdx.x;
    const int tx = tid & 15;   // 16 col groups (4 cols each)
    const int ty = tid >> 4;   // 16 row groups (4 rows each)
    const int row0 = blockIdx.y * 64;
    const int col0 = blockIdx.x * 64;

    const int ar = tid >> 2;   // 0..63  (A rows)
    const int ac = tid & 3;    // 0..3   (A k-chunk of 4)
    const int br = tid >> 4;   // 0..15  (B k rows)
    const int bc = tid & 15;   // 0..15  (B col chunk of 4)

    unsigned long long acc2[2][4];   // [m-pair][n]
#pragma unroll
    for (int mp = 0; mp < 2; mp++)
#pragma unroll
        for (int n = 0; n < 4; n++) acc2[mp][n] = 0ull;

    for (int k0 = 0; k0 < Kd; k0 += 16) {
        float4 av = *(const float4*)(A + (size_t)(row0 + ar) * Kd + k0 + ac * 4);
        As[ac * 4 + 0][ar] = av.x;
        As[ac * 4 + 1][ar] = av.y;
        As[ac * 4 + 2][ar] = av.z;
        As[ac * 4 + 3][ar] = av.w;
        *(float4*)&Bs[br][bc * 4] =
            *(const float4*)(B + (size_t)(k0 + br) * N + col0 + bc * 4);
        __syncthreads();

#pragma unroll
        for (int k = 0; k < 16; k++) {
            ulonglong2 a01 = *(const ulonglong2*)&As[k][ty * 4];
            float4 b4 = *(const float4*)&Bs[k][tx * 4];
            unsigned long long bb0 = pack2(b4.x, b4.x);
            unsigned long long bb1 = pack2(b4.y, b4.y);
            unsigned long long bb2 = pack2(b4.z, b4.z);
            unsigned long long bb3 = pack2(b4.w, b4.w);
            acc2[0][0] = ffma2(a01.x, bb0, acc2[0][0]);
            acc2[0][1] = ffma2(a01.x, bb1, acc2[0][1]);
            acc2[0][2] = ffma2(a01.x, bb2, acc2[0][2]);
            acc2[0][3] = ffma2(a01.x, bb3, acc2[0][3]);
            acc2[1][0] = ffma2(a01.y, bb0, acc2[1][0]);
            acc2[1][1] = ffma2(a01.y, bb1, acc2[1][1]);
            acc2[1][2] = ffma2(a01.y, bb2, acc2[1][2]);
            acc2[1][3] = ffma2(a01.y, bb3, acc2[1][3]);
        }
        __syncthreads();
    }

    float4 bias4 = *(const float4*)(bias + col0 + tx * 4);

    // region info (block-uniform when PACK; BN=64 == one region)
    const int region = col0 >> 6;        // 0..8
    const int kind   = region % 3;       // 0=q 1=k 2=v
    const int scale  = region / 3;
    const int head   = tx >> 3;
    const int ch     = (tx * 4) & 31;
    const int hg     = scale * 2 + head;

#pragma unroll
    for (int mp = 0; mp < 2; mp++) {
        float2 f0 = unpack2(acc2[mp][0]);
        float2 f1 = unpack2(acc2[mp][1]);
        float2 f2 = unpack2(acc2[mp][2]);
        float2 f3 = unpack2(acc2[mp][3]);
        float4 lo = make_float4(f0.x + bias4.x, f1.x + bias4.y,
                                f2.x + bias4.z, f3.x + bias4.w);
        float4 hi = make_float4(f0.y + bias4.x, f1.y + bias4.y,
                                f2.y + bias4.z, f3.y + bias4.w);
        const int r_lo = row0 + ty * 4 + 2 * mp;
        if (!PACK) {
            *(float4*)(C + (size_t)r_lo * N + col0 + tx * 4) = lo;
            *(float4*)(C + (size_t)(r_lo + 1) * N + col0 + tx * 4) = hi;
        } else {
            if (kind == 0) {
                *(float4*)(gq + ((size_t)hg * NV + r_lo) * 32 + ch) = lo;
                *(float4*)(gq + ((size_t)hg * NV + r_lo + 1) * 32 + ch) = hi;
            } else {
                float sc = (kind == 1) ? SCALE_F : 1.0f;
                __half* base = (kind == 1) ? gkh : gvh;
                __half2 l01 = __floats2half2_rn(lo.x * sc, lo.y * sc);
                __half2 l23 = __floats2half2_rn(lo.z * sc, lo.w * sc);
                __half2 h01 = __floats2half2_rn(hi.x * sc, hi.y * sc);
                __half2 h23 = __floats2half2_rn(hi.z * sc, hi.w * sc);
                uint2 ul = make_uint2(*(unsigned*)&l01, *(unsigned*)&l23);
                uint2 uh = make_uint2(*(unsigned*)&h01, *(unsigned*)&h23);
                *(uint2*)(base + ((size_t)hg * NV + r_lo) * 32 + ch) = ul;
                *(uint2*)(base + ((size_t)hg * NV + r_lo + 1) * 32 + ch) = uh;
            }
        }
    }
}

// ---------------------------------------------------------------------------
// NA3D partial-attention over a depth-slice range [d0off, d0off+ncnt).
// 2-lane query split: lane t in {0,1} owns 16 channels (32B) of one query.
// g = ((((head*8+d)*24+h)*24+w)*2 + t  -> warp = 16 w-positions x 2 lanes,
// k/v warp loads ~1KB contiguous. One shfl_xor per logit. Math in HFMA2,
// p*v accumulated in half2 per hh-row, flushed to fp32 (bounded error).
// ---------------------------------------------------------------------------
template <int K>
__device__ __forceinline__ void na_body(
    const float* __restrict__ gq,
    const __half* __restrict__ kh, const __half* __restrict__ vh,
    float* __restrict__ part, int hgbase, int bidx, int d0off, int ncnt)
{
    const int g = bidx * 256 + threadIdx.x;
    const int t = g & 1;
    int r = g >> 1;
    const int w = r % 24; r /= 24;
    const int h = r % 24; r /= 24;
    const int d = r & 7;
    const int head = r >> 3;

    const int start_d = iclamp(d - K / 2, 0, Dd - K);
    const int start_h = iclamp(h - K / 2, 0, Hh - K);
    const int start_w = iclamp(w - K / 2, 0, Ww - K);

    const int hg = hgbase + head;
    const int qrow = (d * Hh + h) * Ww + w;

    // q (16 floats) -> 8 half2 (k is pre-scaled by SCALE)
    const float* qp = gq + ((size_t)hg * NV + qrow) * 32 + t * 16;
    __half2 qh[8];
#pragma unroll
    for (int j = 0; j < 4; j++) {
        float4 qf = *(const float4*)(qp + j * 4);
        qh[2 * j]     = __floats2half2_rn(qf.x, qf.y);
        qh[2 * j + 1] = __floats2half2_rn(qf.z, qf.w);
    }

    const __half* kbase = kh + (size_t)hg * NV * 32 + t * 16;
    const __half* vbase = vh + (size_t)hg * NV * 32 + t * 16;

    float l = 0.f;
    float fa[16];
#pragma unroll
    for (int i = 0; i < 16; i++) fa[i] = 0.f;

    for (int ddi = 0; ddi < ncnt; ddi++) {
        const int dd = start_d + d0off + ddi;
        for (int hh = 0; hh < K; hh++) {
            const int rowbase = (dd * Hh + start_h + hh) * Ww + start_w;
            __half2 a2[8];
#pragma unroll
            for (int j = 0; j < 8; j++) a2[j] = __floats2half2_rn(0.f, 0.f);
#pragma unroll
            for (int ww = 0; ww < K; ww++) {
                const int row = rowbase + ww;
                const uint4 ka = *(const uint4*)(kbase + (size_t)row * 32);
                const uint4 kb = *(const uint4*)(kbase + (size_t)row * 32 + 8);
                __half2 s2 = __hmul2(qh[0], *(const __half2*)&ka.x);
                s2 = __hfma2(qh[1], *(const __half2*)&ka.y, s2);
                s2 = __hfma2(qh[2], *(const __half2*)&ka.z, s2);
                s2 = __hfma2(qh[3], *(const __half2*)&ka.w, s2);
                s2 = __hfma2(qh[4], *(const __half2*)&kb.x, s2);
                s2 = __hfma2(qh[5], *(const __half2*)&kb.y, s2);
                s2 = __hfma2(qh[6], *(const __half2*)&kb.z, s2);
                s2 = __hfma2(qh[7], *(const __half2*)&kb.w, s2);
                float2 sf = __half22float2(s2);
                float s = sf.x + sf.y;
                s += __shfl_xor_sync(0xffffffffu, s, 1);

                float p = __expf(s);
                l += p;
                __half2 pp = __half2half2(__float2half_rn(p));
                const uint4 va = *(const uint4*)(vbase + (size_t)row * 32);
                const uint4 vb = *(const uint4*)(vbase + (size_t)row * 32 + 8);
                a2[0] = __hfma2(pp, *(const __half2*)&va.x, a2[0]);
                a2[1] = __hfma2(pp, *(const __half2*)&va.y, a2[1]);
                a2[2] = __hfma2(pp, *(const __half2*)&va.z, a2[2]);
                a2[3] = __hfma2(pp, *(const __half2*)&va.w, a2[3]);
                a2[4] = __hfma2(pp, *(const __half2*)&vb.x, a2[4]);
                a2[5] = __hfma2(pp, *(const __half2*)&vb.y, a2[5]);
                a2[6] = __hfma2(pp, *(const __half2*)&vb.z, a2[6]);
                a2[7] = __hfma2(pp, *(const __half2*)&vb.w, a2[7]);
            }
#pragma unroll
            for (int j = 0; j < 8; j++) {
                float2 fj = __half22float2(a2[j]);
                fa[2 * j]     += fj.x;
                fa[2 * j + 1] += fj.y;
            }
        }
    }

    const int qidx = ((head * Dd + d) * Hh + h) * Ww + w;  // 0..QPS-1
    float* pb = part + (size_t)qidx * PART_STRIDE + t * 16;
#pragma unroll
    for (int j = 0; j < 4; j++)
        *(float4*)(pb + j * 4) = make_float4(fa[4 * j], fa[4 * j + 1],
                                             fa[4 * j + 2], fa[4 * j + 3]);
    if (t == 0) part[(size_t)qidx * PART_STRIDE + 32] = l;
}

// One launch, all scales+chunks. 72 blocks per chunk; heavy K7 chunks first.
__global__ __launch_bounds__(256) void na_partial_all_kernel(
    const float* __restrict__ gq,
    const __half* __restrict__ kh, const __half* __restrict__ vh,
    float* __restrict__ part)
{
    const int b = blockIdx.x;
    if (b < 72)        na_body<7>(gq, kh, vh, part + 3 * (size_t)PART_UNIT, 4, b,       0, 3);
    else if (b < 144)  na_body<7>(gq, kh, vh, part + 4 * (size_t)PART_UNIT, 4, b - 72,  3, 2);
    else if (b < 216)  na_body<7>(gq, kh, vh, part + 5 * (size_t)PART_UNIT, 4, b - 144, 5, 2);
    else if (b < 288)  na_body<5>(gq, kh, vh, part + 1 * (size_t)PART_UNIT, 2, b - 216, 0, 3);
    else if (b < 360)  na_body<5>(gq, kh, vh, part + 2 * (size_t)PART_UNIT, 2, b - 288, 3, 2);
    else               na_body<3>(gq, kh, vh, part + 0 * (size_t)PART_UNIT, 0, b - 360, 0, 3);
}

// ---------------------------------------------------------------------------
// Combine partials (plain sums) across chunks -> g_y. 110592 threads.
// ---------------------------------------------------------------------------
__global__ __launch_bounds__(256) void na_combine_kernel(
    const float* __restrict__ part, float* __restrict__ y)
{
    const int g = blockIdx.x * 256 + threadIdx.x;
    const int t = g & 3;
    int r = g >> 2;
    const int w = r % 24; r /= 24;
    const int h = r % 24; r /= 24;
    const int d = r & 7;  r >>= 3;
    const int head = r & 1;
    const int s = r >> 1;            // scale 0..2

    const int cnt = s + 1;
    const size_t base = (size_t)PART_UNIT * (size_t)(s * (s + 1) / 2);
    const int qidx = ((head * Dd + d) * Hh + h) * Ww + w;

    float L = 0.f;
    float o[8];
#pragma unroll
    for (int i = 0; i < 8; i++) o[i] = 0.f;
    for (int c = 0; c < cnt; c++) {
        const float* pb = part + base + (size_t)c * PART_UNIT
                        + (size_t)qidx * PART_STRIDE;
        L += pb[32];
        float4 a0 = *(const float4*)(pb + t * 8);
        float4 a1 = *(const float4*)(pb + t * 8 + 4);
        o[0] += a0.x; o[1] += a0.y; o[2] += a0.z; o[3] += a0.w;
        o[4] += a1.x; o[5] += a1.y; o[6] += a1.z; o[7] += a1.w;
    }
    float inv = 1.f / L;
    const int vr = (d * Hh + h) * Ww + w;
    float* yp = y + (size_t)vr * DIMC + s * 64 + head * 32 + t * 8;
    *(float4*)yp       = make_float4(o[0] * inv, o[1] * inv, o[2] * inv, o[3] * inv);
    *(float4*)(yp + 4) = make_float4(o[4] * inv, o[5] * inv, o[6] * inv, o[7] * inv);
}

// ---------------------------------------------------------------------------
// Launch
// ---------------------------------------------------------------------------
extern "C" void kernel_launch(void* const* d_in, const int* in_sizes, int n_in,
                              void* d_out, int out_size)
{
    (void)in_sizes; (void)n_in; (void)out_size;
    const float* x      = (const float*)d_in[0];
    const float* W_qkv  = (const float*)d_in[1];
    const float* b_qkv  = (const float*)d_in[2];
    const float* W_proj = (const float*)d_in[3];
    const float* b_proj = (const float*)d_in[4];
    float* out = (float*)d_out;

    float*  gq;   cudaGetSymbolAddress((void**)&gq,   g_q);
    __half* kh;   cudaGetSymbolAddress((void**)&kh,   g_kh);
    __half* vh;   cudaGetSymbolAddress((void**)&vh,   g_vh);
    float*  y;    cudaGetSymbolAddress((void**)&y,    g_y);
    float*  part; cudaGetSymbolAddress((void**)&part, g_part);

    // 1) fused QKV GEMM + pack (648 blocks)
    gemm_bias_kernel<true><<<dim3(576 / 64, NV / 64), 256>>>(
        x, W_qkv, b_qkv, nullptr, gq, kh, vh, NV, 576, DIMC);

    // 2) all-scale NA3D partials, one launch (432 blocks)
    na_partial_all_kernel<<<432, 256>>>(gq, kh, vh, part);

    // 3) combine partials -> y
    na_combine_kernel<<<110592 / 256, 256>>>(part, y);

    // 4) out = y @ W_proj + b_proj (216 blocks)
    gemm_bias_kernel<false><<<dim3(DIMC / 64, NV / 64), 256>>>(
        y, W_proj, b_proj, out, nullptr, nullptr, nullptr, NV, DIMC, DIMC);
}

// round 6
// speedup vs baseline: 1.0449x; 1.0449x over previous
#include <cuda_runtime.h>
#include <cuda_fp16.h>

// ---------------------------------------------------------------------------
// Problem constants
// ---------------------------------------------------------------------------
#define Dd 8
#define Hh 24
#define Ww 24
#define NV (Dd * Hh * Ww)     /* 4608 voxels */
#define DIMC 192
#define QPS (2 * NV)          /* queries per scale: 2 heads * 4608 = 9216 */
#define PART_STRIDE 36        /* floats per partial record: 32 acc + l + pad */
#define PART_UNIT (QPS * PART_STRIDE)
#define SCALE_F 0.17677669529663687f  /* 32^-0.5 */

static __device__ __align__(16) float  g_q[6 * NV * 32];         // 3.5 MB packed fp32 Q
static __device__ __align__(16) __half g_kh[6 * NV * 32];        // 1.7 MB packed K fp16 (pre-scaled)
static __device__ __align__(16) __half g_vh[6 * NV * 32];        // 1.7 MB packed V fp16
static __device__ __align__(16) float  g_y[NV * DIMC];           // 3.5 MB
static __device__ __align__(16) float  g_part[6 * PART_UNIT];    // 8.0 MB partials
static __device__ __align__(16) float  g_psum[2 * NV * DIMC];    // 7.1 MB split-K partials

__device__ __forceinline__ int iclamp(int v, int lo, int hi) {
    v = v < lo ? lo : v;
    return v > hi ? hi : v;
}

// ---------------------------------------------------------------------------
// Packed f32x2 helpers (FFMA2 path — 2x FFMA throughput on sm_103a)
// ---------------------------------------------------------------------------
__device__ __forceinline__ unsigned long long pack2(float x, float y) {
    unsigned long long r;
    asm("mov.b64 %0, {%1, %2};" : "=l"(r) : "f"(x), "f"(y));
    return r;
}
__device__ __forceinline__ float2 unpack2(unsigned long long u) {
    float2 r;
    asm("mov.b64 {%0, %1}, %2;" : "=f"(r.x), "=f"(r.y) : "l"(u));
    return r;
}
__device__ __forceinline__ unsigned long long ffma2(
    unsigned long long a, unsigned long long b, unsigned long long c) {
    unsigned long long d;
    asm("fma.rn.f32x2 %0, %1, %2, %3;" : "=l"(d) : "l"(a), "l"(b), "l"(c));
    return d;
}

// ---------------------------------------------------------------------------
// GEMM: C[M,N] (+= over k-range) = A[M,k-range] @ B[k-range,N] (+ bias)
// BM=128, BN=64, BK=16, 256 threads, 8x4 register tile (FFMA2, m-paired).
// DOUBLE-BUFFERED smem: LDG of tile t+1 overlaps compute of tile t; one
// __syncthreads per k-tile. Split-K via (k0off, nkt): computes a partial sum.
// PACK=true (QKV GEMM): scatter q fp32 packed, k(*SCALE)/v fp16 packed.
// ---------------------------------------------------------------------------
template <bool PACK>
__global__ __launch_bounds__(256) void gemm_bias_kernel(
    const float* __restrict__ A, const float* __restrict__ B,
    const float* __restrict__ bias, float* __restrict__ C,
    float* __restrict__ gq, __half* __restrict__ gkh, __half* __restrict__ gvh,
    int M, int N, int Kd, int k0off, int nkt, int addbias)
{
    __shared__ __align__(16) float As[2][16][132];
    __shared__ __align__(16) float Bs[2][16][64];

    const int tid = threadIdx.x;
    const int tx = tid & 15;   // 16 col groups (4 cols each)
    const int ty = tid >> 4;   // 16 row groups (8 rows each)
    const int row0 = blockIdx.y * 128;
    const int col0 = blockIdx.x * 64;

    const int ar = tid >> 2;   // 0..63  (A rows, x2)
    const int ac = tid & 3;    // 0..3   (A k-chunk of 4)
    const int br = tid >> 4;   // 0..15  (B k rows)
    const int bc = tid & 15;   // 0..15  (B col chunk of 4)

    const float* Abase = A + (size_t)(row0 + ar) * Kd + ac * 4;
    const float* Bbase = B + (size_t)br * N + col0 + bc * 4;

    unsigned long long acc2[4][4];   // [m-pair][n]
#pragma unroll
    for (int mp = 0; mp < 4; mp++)
#pragma unroll
        for (int n = 0; n < 4; n++) acc2[mp][n] = 0ull;

    // prologue: load tile 0 into stage 0
    float4 a0v = *(const float4*)(Abase + k0off);
    float4 a1v = *(const float4*)(Abase + (size_t)64 * Kd + k0off);
    float4 bv  = *(const float4*)(Bbase + (size_t)k0off * N);
    As[0][ac * 4 + 0][ar] = a0v.x;  As[0][ac * 4 + 1][ar] = a0v.y;
    As[0][ac * 4 + 2][ar] = a0v.z;  As[0][ac * 4 + 3][ar] = a0v.w;
    As[0][ac * 4 + 0][ar + 64] = a1v.x;  As[0][ac * 4 + 1][ar + 64] = a1v.y;
    As[0][ac * 4 + 2][ar + 64] = a1v.z;  As[0][ac * 4 + 3][ar + 64] = a1v.w;
    *(float4*)&Bs[0][br][bc * 4] = bv;
    __syncthreads();

    int buf = 0;
    for (int t = 0; t < nkt; t++) {
        const bool more = (t + 1 < nkt);
        if (more) {
            const int kq = k0off + (t + 1) * 16;
            a0v = *(const float4*)(Abase + kq);
            a1v = *(const float4*)(Abase + (size_t)64 * Kd + kq);
            bv  = *(const float4*)(Bbase + (size_t)kq * N);
        }

#pragma unroll
        for (int k = 0; k < 16; k++) {
            const ulonglong2* Ap = (const ulonglong2*)&As[buf][k][ty * 8];
            ulonglong2 a01 = Ap[0];
            ulonglong2 a23 = Ap[1];
            float4 b4 = *(const float4*)&Bs[buf][k][tx * 4];
            unsigned long long bb0 = pack2(b4.x, b4.x);
            unsigned long long bb1 = pack2(b4.y, b4.y);
            unsigned long long bb2 = pack2(b4.z, b4.z);
            unsigned long long bb3 = pack2(b4.w, b4.w);
            acc2[0][0] = ffma2(a01.x, bb0, acc2[0][0]);
            acc2[0][1] = ffma2(a01.x, bb1, acc2[0][1]);
            acc2[0][2] = ffma2(a01.x, bb2, acc2[0][2]);
            acc2[0][3] = ffma2(a01.x, bb3, acc2[0][3]);
            acc2[1][0] = ffma2(a01.y, bb0, acc2[1][0]);
            acc2[1][1] = ffma2(a01.y, bb1, acc2[1][1]);
            acc2[1][2] = ffma2(a01.y, bb2, acc2[1][2]);
            acc2[1][3] = ffma2(a01.y, bb3, acc2[1][3]);
            acc2[2][0] = ffma2(a23.x, bb0, acc2[2][0]);
            acc2[2][1] = ffma2(a23.x, bb1, acc2[2][1]);
            acc2[2][2] = ffma2(a23.x, bb2, acc2[2][2]);
            acc2[2][3] = ffma2(a23.x, bb3, acc2[2][3]);
            acc2[3][0] = ffma2(a23.y, bb0, acc2[3][0]);
            acc2[3][1] = ffma2(a23.y, bb1, acc2[3][1]);
            acc2[3][2] = ffma2(a23.y, bb2, acc2[3][2]);
            acc2[3][3] = ffma2(a23.y, bb3, acc2[3][3]);
        }

        if (more) {
            const int nb = buf ^ 1;
            As[nb][ac * 4 + 0][ar] = a0v.x;  As[nb][ac * 4 + 1][ar] = a0v.y;
            As[nb][ac * 4 + 2][ar] = a0v.z;  As[nb][ac * 4 + 3][ar] = a0v.w;
            As[nb][ac * 4 + 0][ar + 64] = a1v.x;  As[nb][ac * 4 + 1][ar + 64] = a1v.y;
            As[nb][ac * 4 + 2][ar + 64] = a1v.z;  As[nb][ac * 4 + 3][ar + 64] = a1v.w;
            *(float4*)&Bs[nb][br][bc * 4] = bv;
            __syncthreads();
            buf = nb;
        }
    }

    float4 bias4 = addbias ? *(const float4*)(bias + col0 + tx * 4)
                           : make_float4(0.f, 0.f, 0.f, 0.f);

    // region info (block-uniform when PACK)
    const int region = col0 >> 6;        // 0..8
    const int kind   = region % 3;       // 0=q 1=k 2=v
    const int scale  = region / 3;
    const int head   = tx >> 3;
    const int ch     = (tx * 4) & 31;
    const int hg     = scale * 2 + head;

#pragma unroll
    for (int mp = 0; mp < 4; mp++) {
        float2 f0 = unpack2(acc2[mp][0]);
        float2 f1 = unpack2(acc2[mp][1]);
        float2 f2 = unpack2(acc2[mp][2]);
        float2 f3 = unpack2(acc2[mp][3]);
        float4 lo = make_float4(f0.x + bias4.x, f1.x + bias4.y,
                                f2.x + bias4.z, f3.x + bias4.w);
        float4 hi = make_float4(f0.y + bias4.x, f1.y + bias4.y,
                                f2.y + bias4.z, f3.y + bias4.w);
        const int r_lo = row0 + ty * 8 + 2 * mp;
        if (!PACK) {
            *(float4*)(C + (size_t)r_lo * N + col0 + tx * 4) = lo;
            *(float4*)(C + (size_t)(r_lo + 1) * N + col0 + tx * 4) = hi;
        } else {
            if (kind == 0) {
                *(float4*)(gq + ((size_t)hg * NV + r_lo) * 32 + ch) = lo;
                *(float4*)(gq + ((size_t)hg * NV + r_lo + 1) * 32 + ch) = hi;
            } else {
                float sc = (kind == 1) ? SCALE_F : 1.0f;
                __half* base = (kind == 1) ? gkh : gvh;
                __half2 l01 = __floats2half2_rn(lo.x * sc, lo.y * sc);
                __half2 l23 = __floats2half2_rn(lo.z * sc, lo.w * sc);
                __half2 h01 = __floats2half2_rn(hi.x * sc, hi.y * sc);
                __half2 h23 = __floats2half2_rn(hi.z * sc, hi.w * sc);
                uint2 ul = make_uint2(*(unsigned*)&l01, *(unsigned*)&l23);
                uint2 uh = make_uint2(*(unsigned*)&h01, *(unsigned*)&h23);
                *(uint2*)(base + ((size_t)hg * NV + r_lo) * 32 + ch) = ul;
                *(uint2*)(base + ((size_t)hg * NV + r_lo + 1) * 32 + ch) = uh;
            }
        }
    }
}

// Split-K reduction: out = p0 + p1 + bias. 221184 float4 threads.
__global__ __launch_bounds__(256) void splitk_reduce_kernel(
    const float* __restrict__ p0, const float* __restrict__ p1,
    const float* __restrict__ bias, float* __restrict__ out)
{
    const int i = (blockIdx.x * 256 + threadIdx.x) * 4;
    float4 a = *(const float4*)(p0 + i);
    float4 b = *(const float4*)(p1 + i);
    float4 bi = *(const float4*)(bias + (i % DIMC));
    *(float4*)(out + i) = make_float4(a.x + b.x + bi.x, a.y + b.y + bi.y,
                                      a.z + b.z + bi.z, a.w + b.w + bi.w);
}

// ---------------------------------------------------------------------------
// NA3D partial-attention over a depth-slice range [d0off, d0off+ncnt).
// 4-lane query split (R4 config): lane t in {0..3} owns 8 channels.
// Math in HFMA2; p*v accumulated in half2 per hh-row, flushed to fp32.
// No-max softmax (logits tiny). Partial = (sum p*v, sum p).
// ---------------------------------------------------------------------------
template <int K>
__device__ __forceinline__ void na_body(
    const float* __restrict__ gq,
    const __half* __restrict__ kh, const __half* __restrict__ vh,
    float* __restrict__ part, int hgbase, int bidx, int d0off, int ncnt)
{
    const int g = bidx * 256 + threadIdx.x;
    const int t = g & 3;
    int r = g >> 2;
    const int w = r % 24; r /= 24;
    const int h = r % 24; r /= 24;
    const int d = r & 7;
    const int head = r >> 3;

    const int start_d = iclamp(d - K / 2, 0, Dd - K);
    const int start_h = iclamp(h - K / 2, 0, Hh - K);
    const int start_w = iclamp(w - K / 2, 0, Ww - K);

    const int hg = hgbase + head;
    const int qrow = (d * Hh + h) * Ww + w;

    // q (8 floats) -> 4 half2 (k is pre-scaled by SCALE)
    const float* qp = gq + ((size_t)hg * NV + qrow) * 32 + t * 8;
    float4 q0 = *(const float4*)qp;
    float4 q1 = *(const float4*)(qp + 4);
    __half2 qh[4];
    qh[0] = __floats2half2_rn(q0.x, q0.y);
    qh[1] = __floats2half2_rn(q0.z, q0.w);
    qh[2] = __floats2half2_rn(q1.x, q1.y);
    qh[3] = __floats2half2_rn(q1.z, q1.w);

    const __half* kbase = kh + (size_t)hg * NV * 32 + t * 8;
    const __half* vbase = vh + (size_t)hg * NV * 32 + t * 8;

    float l = 0.f;
    float fa[8];
#pragma unroll
    for (int i = 0; i < 8; i++) fa[i] = 0.f;

    for (int ddi = 0; ddi < ncnt; ddi++) {
        const int dd = start_d + d0off + ddi;
        for (int hh = 0; hh < K; hh++) {
            const int rowbase = (dd * Hh + start_h + hh) * Ww + start_w;
            __half2 a2[4];
            a2[0] = a2[1] = a2[2] = a2[3] = __floats2half2_rn(0.f, 0.f);
#pragma unroll
            for (int ww = 0; ww < K; ww++) {
                const int row = rowbase + ww;
                const uint4 k4 = *(const uint4*)(kbase + (size_t)row * 32);
                __half2 s2 = __hmul2(qh[0], *(const __half2*)&k4.x);
                s2 = __hfma2(qh[1], *(const __half2*)&k4.y, s2);
                s2 = __hfma2(qh[2], *(const __half2*)&k4.z, s2);
                s2 = __hfma2(qh[3], *(const __half2*)&k4.w, s2);
                float2 sf = __half22float2(s2);
                float s = sf.x + sf.y;
                s += __shfl_xor_sync(0xffffffffu, s, 1);
                s += __shfl_xor_sync(0xffffffffu, s, 2);

                float p = __expf(s);
                l += p;
                __half2 pp = __half2half2(__float2half_rn(p));
                const uint4 v4 = *(const uint4*)(vbase + (size_t)row * 32);
                a2[0] = __hfma2(pp, *(const __half2*)&v4.x, a2[0]);
                a2[1] = __hfma2(pp, *(const __half2*)&v4.y, a2[1]);
                a2[2] = __hfma2(pp, *(const __half2*)&v4.z, a2[2]);
                a2[3] = __hfma2(pp, *(const __half2*)&v4.w, a2[3]);
            }
#pragma unroll
            for (int j = 0; j < 4; j++) {
                float2 fj = __half22float2(a2[j]);
                fa[2 * j]     += fj.x;
                fa[2 * j + 1] += fj.y;
            }
        }
    }

    const int qidx = ((head * Dd + d) * Hh + h) * Ww + w;  // 0..QPS-1
    float* pb = part + (size_t)qidx * PART_STRIDE;
    *(float4*)(pb + t * 8)     = make_float4(fa[0], fa[1], fa[2], fa[3]);
    *(float4*)(pb + t * 8 + 4) = make_float4(fa[4], fa[5], fa[6], fa[7]);
    if (t == 0) pb[32] = l;
}

// One launch, all scales+chunks. 144 blocks per chunk; heavy K7 chunks first.
__global__ __launch_bounds__(256) void na_partial_all_kernel(
    const float* __restrict__ gq,
    const __half* __restrict__ kh, const __half* __restrict__ vh,
    float* __restrict__ part)
{
    const int b = blockIdx.x;
    if (b < 144)       na_body<7>(gq, kh, vh, part + 3 * (size_t)PART_UNIT, 4, b,       0, 3);
    else if (b < 288)  na_body<7>(gq, kh, vh, part + 4 * (size_t)PART_UNIT, 4, b - 144, 3, 2);
    else if (b < 432)  na_body<7>(gq, kh, vh, part + 5 * (size_t)PART_UNIT, 4, b - 288, 5, 2);
    else if (b < 576)  na_body<5>(gq, kh, vh, part + 1 * (size_t)PART_UNIT, 2, b - 432, 0, 3);
    else if (b < 720)  na_body<5>(gq, kh, vh, part + 2 * (size_t)PART_UNIT, 2, b - 576, 3, 2);
    else               na_body<3>(gq, kh, vh, part + 0 * (size_t)PART_UNIT, 0, b - 720, 0, 3);
}

// ---------------------------------------------------------------------------
// Combine partials (plain sums) across chunks -> g_y. 110592 threads.
// ---------------------------------------------------------------------------
__global__ __launch_bounds__(256) void na_combine_kernel(
    const float* __restrict__ part, float* __restrict__ y)
{
    const int g = blockIdx.x * 256 + threadIdx.x;
    const int t = g & 3;
    int r = g >> 2;
    const int w = r % 24; r /= 24;
    const int h = r % 24; r /= 24;
    const int d = r & 7;  r >>= 3;
    const int head = r & 1;
    const int s = r >> 1;            // scale 0..2

    const int cnt = s + 1;
    const size_t base = (size_t)PART_UNIT * (size_t)(s * (s + 1) / 2);
    const int qidx = ((head * Dd + d) * Hh + h) * Ww + w;

    float L = 0.f;
    float o[8];
#pragma unroll
    for (int i = 0; i < 8; i++) o[i] = 0.f;
    for (int c = 0; c < cnt; c++) {
        const float* pb = part + base + (size_t)c * PART_UNIT
                        + (size_t)qidx * PART_STRIDE;
        L += pb[32];
        float4 a0 = *(const float4*)(pb + t * 8);
        float4 a1 = *(const float4*)(pb + t * 8 + 4);
        o[0] += a0.x; o[1] += a0.y; o[2] += a0.z; o[3] += a0.w;
        o[4] += a1.x; o[5] += a1.y; o[6] += a1.z; o[7] += a1.w;
    }
    float inv = 1.f / L;
    const int vr = (d * Hh + h) * Ww + w;
    float* yp = y + (size_t)vr * DIMC + s * 64 + head * 32 + t * 8;
    *(float4*)yp       = make_float4(o[0] * inv, o[1] * inv, o[2] * inv, o[3] * inv);
    *(float4*)(yp + 4) = make_float4(o[4] * inv, o[5] * inv, o[6] * inv, o[7] * inv);
}

// ---------------------------------------------------------------------------
// Launch
// ---------------------------------------------------------------------------
extern "C" void kernel_launch(void* const* d_in, const int* in_sizes, int n_in,
                              void* d_out, int out_size)
{
    (void)in_sizes; (void)n_in; (void)out_size;
    const float* x      = (const float*)d_in[0];
    const float* W_qkv  = (const float*)d_in[1];
    const float* b_qkv  = (const float*)d_in[2];
    const float* W_proj = (const float*)d_in[3];
    const float* b_proj = (const float*)d_in[4];
    float* out = (float*)d_out;

    float*  gq;   cudaGetSymbolAddress((void**)&gq,   g_q);
    __half* kh;   cudaGetSymbolAddress((void**)&kh,   g_kh);
    __half* vh;   cudaGetSymbolAddress((void**)&vh,   g_vh);
    float*  y;    cudaGetSymbolAddress((void**)&y,    g_y);
    float*  part; cudaGetSymbolAddress((void**)&part, g_part);
    float*  psum; cudaGetSymbolAddress((void**)&psum, g_psum);

    // 1) fused QKV GEMM + pack (324 blocks, double-buffered, full K)
    gemm_bias_kernel<true><<<dim3(576 / 64, NV / 128), 256>>>(
        x, W_qkv, b_qkv, nullptr, gq, kh, vh, NV, 576, DIMC, 0, 12, 1);

    // 2) all-scale NA3D partials, one launch (864 blocks)
    na_partial_all_kernel<<<864, 256>>>(gq, kh, vh, part);

    // 3) combine partials -> y
    na_combine_kernel<<<110592 / 256, 256>>>(part, y);

    // 4) proj GEMM, split-K=2 (2 x 108 independent blocks) -> psum halves
    gemm_bias_kernel<false><<<dim3(DIMC / 64, NV / 128), 256>>>(
        y, W_proj, b_proj, psum, nullptr, nullptr, nullptr, NV, DIMC, DIMC, 0, 6, 0);
    gemm_bias_kernel<false><<<dim3(DIMC / 64, NV / 128), 256>>>(
        y, W_proj, b_proj, psum + (size_t)NV * DIMC, nullptr, nullptr, nullptr,
        NV, DIMC, DIMC, 96, 6, 0);

    // 5) out = psum0 + psum1 + bias
    splitk_reduce_kernel<<<(NV * DIMC / 4) / 256, 256>>>(
        psum, psum + (size_t)NV * DIMC, b_proj, out);
}

// round 7
// speedup vs baseline: 1.0914x; 1.0445x over previous
#include <cuda_runtime.h>
#include <cuda_fp16.h>

// ---------------------------------------------------------------------------
// Problem constants
// ---------------------------------------------------------------------------
#define Dd 8
#define Hh 24
#define Ww 24
#define NV (Dd * Hh * Ww)     /* 4608 voxels */
#define DIMC 192
#define QPS (2 * NV)          /* queries per scale: 2 heads * 4608 = 9216 */
#define PART_STRIDE 36        /* floats per partial record: 32 acc + l + pad */
#define PART_UNIT (QPS * PART_STRIDE)
#define SCALE_F 0.17677669529663687f  /* 32^-0.5 */

static __device__ __align__(16) float  g_q[6 * NV * 32];         // 3.5 MB packed fp32 Q
static __device__ __align__(16) __half g_kh[6 * NV * 32];        // 1.7 MB packed K fp16 (pre-scaled)
static __device__ __align__(16) __half g_vh[6 * NV * 32];        // 1.7 MB packed V fp16
static __device__ __align__(16) float  g_y[NV * DIMC];           // 3.5 MB
static __device__ __align__(16) float  g_part[6 * PART_UNIT];    // 8.0 MB partials
static __device__ __align__(16) float  g_psum[4 * NV * DIMC];    // 14.2 MB split-K partials

__device__ __forceinline__ int iclamp(int v, int lo, int hi) {
    v = v < lo ? lo : v;
    return v > hi ? hi : v;
}

// ---------------------------------------------------------------------------
// Packed f32x2 helpers (FFMA2 path — 2x FFMA throughput on sm_103a)
// ---------------------------------------------------------------------------
__device__ __forceinline__ unsigned long long pack2(float x, float y) {
    unsigned long long r;
    asm("mov.b64 %0, {%1, %2};" : "=l"(r) : "f"(x), "f"(y));
    return r;
}
__device__ __forceinline__ float2 unpack2(unsigned long long u) {
    float2 r;
    asm("mov.b64 {%0, %1}, %2;" : "=f"(r.x), "=f"(r.y) : "l"(u));
    return r;
}
__device__ __forceinline__ unsigned long long ffma2(
    unsigned long long a, unsigned long long b, unsigned long long c) {
    unsigned long long d;
    asm("fma.rn.f32x2 %0, %1, %2, %3;" : "=l"(d) : "l"(a), "l"(b), "l"(c));
    return d;
}

// ---------------------------------------------------------------------------
// GEMM1 (QKV, PACK): C/packed = A[M,K] @ B[K,N] + bias.
// BM=128, BN=64, BK=16, 256 threads, 8x4 tile, double-buffered smem.
// ---------------------------------------------------------------------------
__global__ __launch_bounds__(256) void gemm_qkv_kernel(
    const float* __restrict__ A, const float* __restrict__ B,
    const float* __restrict__ bias,
    float* __restrict__ gq, __half* __restrict__ gkh, __half* __restrict__ gvh,
    int M, int N, int Kd)
{
    __shared__ __align__(16) float As[2][16][132];
    __shared__ __align__(16) float Bs[2][16][64];

    const int tid = threadIdx.x;
    const int tx = tid & 15;
    const int ty = tid >> 4;
    const int row0 = blockIdx.y * 128;
    const int col0 = blockIdx.x * 64;

    const int ar = tid >> 2;
    const int ac = tid & 3;
    const int br = tid >> 4;
    const int bc = tid & 15;

    const float* Abase = A + (size_t)(row0 + ar) * Kd + ac * 4;
    const float* Bbase = B + (size_t)br * N + col0 + bc * 4;

    unsigned long long acc2[4][4];
#pragma unroll
    for (int mp = 0; mp < 4; mp++)
#pragma unroll
        for (int n = 0; n < 4; n++) acc2[mp][n] = 0ull;

    float4 a0v = *(const float4*)(Abase);
    float4 a1v = *(const float4*)(Abase + (size_t)64 * Kd);
    float4 bv  = *(const float4*)(Bbase);
    As[0][ac * 4 + 0][ar] = a0v.x;  As[0][ac * 4 + 1][ar] = a0v.y;
    As[0][ac * 4 + 2][ar] = a0v.z;  As[0][ac * 4 + 3][ar] = a0v.w;
    As[0][ac * 4 + 0][ar + 64] = a1v.x;  As[0][ac * 4 + 1][ar + 64] = a1v.y;
    As[0][ac * 4 + 2][ar + 64] = a1v.z;  As[0][ac * 4 + 3][ar + 64] = a1v.w;
    *(float4*)&Bs[0][br][bc * 4] = bv;
    __syncthreads();

    const int nkt = Kd / 16;
    int buf = 0;
    for (int t = 0; t < nkt; t++) {
        const bool more = (t + 1 < nkt);
        if (more) {
            const int kq = (t + 1) * 16;
            a0v = *(const float4*)(Abase + kq);
            a1v = *(const float4*)(Abase + (size_t)64 * Kd + kq);
            bv  = *(const float4*)(Bbase + (size_t)kq * N);
        }

#pragma unroll
        for (int k = 0; k < 16; k++) {
            const ulonglong2* Ap = (const ulonglong2*)&As[buf][k][ty * 8];
            ulonglong2 a01 = Ap[0];
            ulonglong2 a23 = Ap[1];
            float4 b4 = *(const float4*)&Bs[buf][k][tx * 4];
            unsigned long long bb0 = pack2(b4.x, b4.x);
            unsigned long long bb1 = pack2(b4.y, b4.y);
            unsigned long long bb2 = pack2(b4.z, b4.z);
            unsigned long long bb3 = pack2(b4.w, b4.w);
            acc2[0][0] = ffma2(a01.x, bb0, acc2[0][0]);
            acc2[0][1] = ffma2(a01.x, bb1, acc2[0][1]);
            acc2[0][2] = ffma2(a01.x, bb2, acc2[0][2]);
            acc2[0][3] = ffma2(a01.x, bb3, acc2[0][3]);
            acc2[1][0] = ffma2(a01.y, bb0, acc2[1][0]);
            acc2[1][1] = ffma2(a01.y, bb1, acc2[1][1]);
            acc2[1][2] = ffma2(a01.y, bb2, acc2[1][2]);
            acc2[1][3] = ffma2(a01.y, bb3, acc2[1][3]);
            acc2[2][0] = ffma2(a23.x, bb0, acc2[2][0]);
            acc2[2][1] = ffma2(a23.x, bb1, acc2[2][1]);
            acc2[2][2] = ffma2(a23.x, bb2, acc2[2][2]);
            acc2[2][3] = ffma2(a23.x, bb3, acc2[2][3]);
            acc2[3][0] = ffma2(a23.y, bb0, acc2[3][0]);
            acc2[3][1] = ffma2(a23.y, bb1, acc2[3][1]);
            acc2[3][2] = ffma2(a23.y, bb2, acc2[3][2]);
            acc2[3][3] = ffma2(a23.y, bb3, acc2[3][3]);
        }

        if (more) {
            const int nb = buf ^ 1;
            As[nb][ac * 4 + 0][ar] = a0v.x;  As[nb][ac * 4 + 1][ar] = a0v.y;
            As[nb][ac * 4 + 2][ar] = a0v.z;  As[nb][ac * 4 + 3][ar] = a0v.w;
            As[nb][ac * 4 + 0][ar + 64] = a1v.x;  As[nb][ac * 4 + 1][ar + 64] = a1v.y;
            As[nb][ac * 4 + 2][ar + 64] = a1v.z;  As[nb][ac * 4 + 3][ar + 64] = a1v.w;
            *(float4*)&Bs[nb][br][bc * 4] = bv;
            __syncthreads();
            buf = nb;
        }
    }

    float4 bias4 = *(const float4*)(bias + col0 + tx * 4);

    const int region = col0 >> 6;        // 0..8
    const int kind   = region % 3;       // 0=q 1=k 2=v
    const int scale  = region / 3;
    const int head   = tx >> 3;
    const int ch     = (tx * 4) & 31;
    const int hg     = scale * 2 + head;

#pragma unroll
    for (int mp = 0; mp < 4; mp++) {
        float2 f0 = unpack2(acc2[mp][0]);
        float2 f1 = unpack2(acc2[mp][1]);
        float2 f2 = unpack2(acc2[mp][2]);
        float2 f3 = unpack2(acc2[mp][3]);
        float4 lo = make_float4(f0.x + bias4.x, f1.x + bias4.y,
                                f2.x + bias4.z, f3.x + bias4.w);
        float4 hi = make_float4(f0.y + bias4.x, f1.y + bias4.y,
                                f2.y + bias4.z, f3.y + bias4.w);
        const int r_lo = row0 + ty * 8 + 2 * mp;
        if (kind == 0) {
            *(float4*)(gq + ((size_t)hg * NV + r_lo) * 32 + ch) = lo;
            *(float4*)(gq + ((size_t)hg * NV + r_lo + 1) * 32 + ch) = hi;
        } else {
            float sc = (kind == 1) ? SCALE_F : 1.0f;
            __half* base = (kind == 1) ? gkh : gvh;
            __half2 l01 = __floats2half2_rn(lo.x * sc, lo.y * sc);
            __half2 l23 = __floats2half2_rn(lo.z * sc, lo.w * sc);
            __half2 h01 = __floats2half2_rn(hi.x * sc, hi.y * sc);
            __half2 h23 = __floats2half2_rn(hi.z * sc, hi.w * sc);
            uint2 ul = make_uint2(*(unsigned*)&l01, *(unsigned*)&l23);
            uint2 uh = make_uint2(*(unsigned*)&h01, *(unsigned*)&h23);
            *(uint2*)(base + ((size_t)hg * NV + r_lo) * 32 + ch) = ul;
            *(uint2*)(base + ((size_t)hg * NV + r_lo + 1) * 32 + ch) = uh;
        }
    }
}

// ---------------------------------------------------------------------------
// GEMM2 (proj), split-K=4: psum[z] = A[M, z*48:(z+1)*48] @ B[z-range, N].
// BM=64, BN=64, BK=16, 256 threads, 4x4 tile, double-buffered.
// Grid (N/64, M/64, 4) = 864 blocks -> ~6 resident blocks/SM.
// ---------------------------------------------------------------------------
__global__ __launch_bounds__(256) void gemm_splitk_kernel(
    const float* __restrict__ A, const float* __restrict__ B,
    float* __restrict__ psum, int M, int N, int Kd, int nkt)
{
    __shared__ __align__(16) float As[2][16][68];
    __shared__ __align__(16) float Bs[2][16][64];

    const int tid = threadIdx.x;
    const int tx = tid & 15;
    const int ty = tid >> 4;   // 0..15, 4 rows each
    const int row0 = blockIdx.y * 64;
    const int col0 = blockIdx.x * 64;
    const int k0   = blockIdx.z * nkt * 16;

    const int ar = tid >> 2;   // 0..63
    const int ac = tid & 3;
    const int br = tid >> 4;
    const int bc = tid & 15;

    const float* Abase = A + (size_t)(row0 + ar) * Kd + k0 + ac * 4;
    const float* Bbase = B + (size_t)(k0 + br) * N + col0 + bc * 4;

    unsigned long long acc2[2][4];
#pragma unroll
    for (int mp = 0; mp < 2; mp++)
#pragma unroll
        for (int n = 0; n < 4; n++) acc2[mp][n] = 0ull;

    float4 av = *(const float4*)(Abase);
    float4 bv = *(const float4*)(Bbase);
    As[0][ac * 4 + 0][ar] = av.x;  As[0][ac * 4 + 1][ar] = av.y;
    As[0][ac * 4 + 2][ar] = av.z;  As[0][ac * 4 + 3][ar] = av.w;
    *(float4*)&Bs[0][br][bc * 4] = bv;
    __syncthreads();

    int buf = 0;
    for (int t = 0; t < nkt; t++) {
        const bool more = (t + 1 < nkt);
        if (more) {
            av = *(const float4*)(Abase + (t + 1) * 16);
            bv = *(const float4*)(Bbase + (size_t)((t + 1) * 16) * N);
        }

#pragma unroll
        for (int k = 0; k < 16; k++) {
            ulonglong2 a01 = *(const ulonglong2*)&As[buf][k][ty * 4];
            float4 b4 = *(const float4*)&Bs[buf][k][tx * 4];
            unsigned long long bb0 = pack2(b4.x, b4.x);
            unsigned long long bb1 = pack2(b4.y, b4.y);
            unsigned long long bb2 = pack2(b4.z, b4.z);
            unsigned long long bb3 = pack2(b4.w, b4.w);
            acc2[0][0] = ffma2(a01.x, bb0, acc2[0][0]);
            acc2[0][1] = ffma2(a01.x, bb1, acc2[0][1]);
            acc2[0][2] = ffma2(a01.x, bb2, acc2[0][2]);
            acc2[0][3] = ffma2(a01.x, bb3, acc2[0][3]);
            acc2[1][0] = ffma2(a01.y, bb0, acc2[1][0]);
            acc2[1][1] = ffma2(a01.y, bb1, acc2[1][1]);
            acc2[1][2] = ffma2(a01.y, bb2, acc2[1][2]);
            acc2[1][3] = ffma2(a01.y, bb3, acc2[1][3]);
        }

        if (more) {
            const int nb = buf ^ 1;
            As[nb][ac * 4 + 0][ar] = av.x;  As[nb][ac * 4 + 1][ar] = av.y;
            As[nb][ac * 4 + 2][ar] = av.z;  As[nb][ac * 4 + 3][ar] = av.w;
            *(float4*)&Bs[nb][br][bc * 4] = bv;
            __syncthreads();
            buf = nb;
        }
    }

    float* out = psum + (size_t)blockIdx.z * M * N;
#pragma unroll
    for (int mp = 0; mp < 2; mp++) {
        float2 f0 = unpack2(acc2[mp][0]);
        float2 f1 = unpack2(acc2[mp][1]);
        float2 f2 = unpack2(acc2[mp][2]);
        float2 f3 = unpack2(acc2[mp][3]);
        const int r_lo = row0 + ty * 4 + 2 * mp;
        *(float4*)(out + (size_t)r_lo * N + col0 + tx * 4) =
            make_float4(f0.x, f1.x, f2.x, f3.x);
        *(float4*)(out + (size_t)(r_lo + 1) * N + col0 + tx * 4) =
            make_float4(f0.y, f1.y, f2.y, f3.y);
    }
}

// Split-K reduction: out = p0+p1+p2+p3 + bias. NV*DIMC/4 float4 threads.
__global__ __launch_bounds__(256) void splitk_reduce4_kernel(
    const float* __restrict__ psum, const float* __restrict__ bias,
    float* __restrict__ out)
{
    const int i = (blockIdx.x * 256 + threadIdx.x) * 4;
    const size_t stride = (size_t)NV * DIMC;
    float4 a = *(const float4*)(psum + i);
    float4 b = *(const float4*)(psum + stride + i);
    float4 c = *(const float4*)(psum + 2 * stride + i);
    float4 d = *(const float4*)(psum + 3 * stride + i);
    float4 bi = *(const float4*)(bias + (i % DIMC));
    *(float4*)(out + i) = make_float4(a.x + b.x + c.x + d.x + bi.x,
                                      a.y + b.y + c.y + d.y + bi.y,
                                      a.z + b.z + c.z + d.z + bi.z,
                                      a.w + b.w + c.w + d.w + bi.w);
}

// ---------------------------------------------------------------------------
// NA3D partial-attention over a depth-slice range [d0off, d0off+ncnt).
// 4-lane query split; HFMA2 math; per-row half2 accum flushed to fp32.
// ---------------------------------------------------------------------------
template <int K>
__device__ __forceinline__ void na_body(
    const float* __restrict__ gq,
    const __half* __restrict__ kh, const __half* __restrict__ vh,
    float* __restrict__ part, int hgbase, int bidx, int d0off, int ncnt)
{
    const int g = bidx * 256 + threadIdx.x;
    const int t = g & 3;
    int r = g >> 2;
    const int w = r % 24; r /= 24;
    const int h = r % 24; r /= 24;
    const int d = r & 7;
    const int head = r >> 3;

    const int start_d = iclamp(d - K / 2, 0, Dd - K);
    const int start_h = iclamp(h - K / 2, 0, Hh - K);
    const int start_w = iclamp(w - K / 2, 0, Ww - K);

    const int hg = hgbase + head;
    const int qrow = (d * Hh + h) * Ww + w;

    const float* qp = gq + ((size_t)hg * NV + qrow) * 32 + t * 8;
    float4 q0 = *(const float4*)qp;
    float4 q1 = *(const float4*)(qp + 4);
    __half2 qh[4];
    qh[0] = __floats2half2_rn(q0.x, q0.y);
    qh[1] = __floats2half2_rn(q0.z, q0.w);
    qh[2] = __floats2half2_rn(q1.x, q1.y);
    qh[3] = __floats2half2_rn(q1.z, q1.w);

    const __half* kbase = kh + (size_t)hg * NV * 32 + t * 8;
    const __half* vbase = vh + (size_t)hg * NV * 32 + t * 8;

    float l = 0.f;
    float fa[8];
#pragma unroll
    for (int i = 0; i < 8; i++) fa[i] = 0.f;

    for (int ddi = 0; ddi < ncnt; ddi++) {
        const int dd = start_d + d0off + ddi;
        for (int hh = 0; hh < K; hh++) {
            const int rowbase = (dd * Hh + start_h + hh) * Ww + start_w;
            __half2 a2[4];
            a2[0] = a2[1] = a2[2] = a2[3] = __floats2half2_rn(0.f, 0.f);
#pragma unroll
            for (int ww = 0; ww < K; ww++) {
                const int row = rowbase + ww;
                const uint4 k4 = *(const uint4*)(kbase + (size_t)row * 32);
                __half2 s2 = __hmul2(qh[0], *(const __half2*)&k4.x);
                s2 = __hfma2(qh[1], *(const __half2*)&k4.y, s2);
                s2 = __hfma2(qh[2], *(const __half2*)&k4.z, s2);
                s2 = __hfma2(qh[3], *(const __half2*)&k4.w, s2);
                float2 sf = __half22float2(s2);
                float s = sf.x + sf.y;
                s += __shfl_xor_sync(0xffffffffu, s, 1);
                s += __shfl_xor_sync(0xffffffffu, s, 2);

                float p = __expf(s);
                l += p;
                __half2 pp = __half2half2(__float2half_rn(p));
                const uint4 v4 = *(const uint4*)(vbase + (size_t)row * 32);
                a2[0] = __hfma2(pp, *(const __half2*)&v4.x, a2[0]);
                a2[1] = __hfma2(pp, *(const __half2*)&v4.y, a2[1]);
                a2[2] = __hfma2(pp, *(const __half2*)&v4.z, a2[2]);
                a2[3] = __hfma2(pp, *(const __half2*)&v4.w, a2[3]);
            }
#pragma unroll
            for (int j = 0; j < 4; j++) {
                float2 fj = __half22float2(a2[j]);
                fa[2 * j]     += fj.x;
                fa[2 * j + 1] += fj.y;
            }
        }
    }

    const int qidx = ((head * Dd + d) * Hh + h) * Ww + w;
    float* pb = part + (size_t)qidx * PART_STRIDE;
    *(float4*)(pb + t * 8)     = make_float4(fa[0], fa[1], fa[2], fa[3]);
    *(float4*)(pb + t * 8 + 4) = make_float4(fa[4], fa[5], fa[6], fa[7]);
    if (t == 0) pb[32] = l;
}

__global__ __launch_bounds__(256) void na_partial_all_kernel(
    const float* __restrict__ gq,
    const __half* __restrict__ kh, const __half* __restrict__ vh,
    float* __restrict__ part)
{
    const int b = blockIdx.x;
    if (b < 144)       na_body<7>(gq, kh, vh, part + 3 * (size_t)PART_UNIT, 4, b,       0, 3);
    else if (b < 288)  na_body<7>(gq, kh, vh, part + 4 * (size_t)PART_UNIT, 4, b - 144, 3, 2);
    else if (b < 432)  na_body<7>(gq, kh, vh, part + 5 * (size_t)PART_UNIT, 4, b - 288, 5, 2);
    else if (b < 576)  na_body<5>(gq, kh, vh, part + 1 * (size_t)PART_UNIT, 2, b - 432, 0, 3);
    else if (b < 720)  na_body<5>(gq, kh, vh, part + 2 * (size_t)PART_UNIT, 2, b - 576, 3, 2);
    else               na_body<3>(gq, kh, vh, part + 0 * (size_t)PART_UNIT, 0, b - 720, 0, 3);
}

// ---------------------------------------------------------------------------
// Combine partials (plain sums) across chunks -> g_y. 110592 threads.
// ---------------------------------------------------------------------------
__global__ __launch_bounds__(256) void na_combine_kernel(
    const float* __restrict__ part, float* __restrict__ y)
{
    const int g = blockIdx.x * 256 + threadIdx.x;
    const int t = g & 3;
    int r = g >> 2;
    const int w = r % 24; r /= 24;
    const int h = r % 24; r /= 24;
    const int d = r & 7;  r >>= 3;
    const int head = r & 1;
    const int s = r >> 1;

    const int cnt = s + 1;
    const size_t base = (size_t)PART_UNIT * (size_t)(s * (s + 1) / 2);
    const int qidx = ((head * Dd + d) * Hh + h) * Ww + w;

    float L = 0.f;
    float o[8];
#pragma unroll
    for (int i = 0; i < 8; i++) o[i] = 0.f;
    for (int c = 0; c < cnt; c++) {
        const float* pb = part + base + (size_t)c * PART_UNIT
                        + (size_t)qidx * PART_STRIDE;
        L += pb[32];
        float4 a0 = *(const float4*)(pb + t * 8);
        float4 a1 = *(const float4*)(pb + t * 8 + 4);
        o[0] += a0.x; o[1] += a0.y; o[2] += a0.z; o[3] += a0.w;
        o[4] += a1.x; o[5] += a1.y; o[6] += a1.z; o[7] += a1.w;
    }
    float inv = 1.f / L;
    const int vr = (d * Hh + h) * Ww + w;
    float* yp = y + (size_t)vr * DIMC + s * 64 + head * 32 + t * 8;
    *(float4*)yp       = make_float4(o[0] * inv, o[1] * inv, o[2] * inv, o[3] * inv);
    *(float4*)(yp + 4) = make_float4(o[4] * inv, o[5] * inv, o[6] * inv, o[7] * inv);
}

// ---------------------------------------------------------------------------
// Launch
// ---------------------------------------------------------------------------
extern "C" void kernel_launch(void* const* d_in, const int* in_sizes, int n_in,
                              void* d_out, int out_size)
{
    (void)in_sizes; (void)n_in; (void)out_size;
    const float* x      = (const float*)d_in[0];
    const float* W_qkv  = (const float*)d_in[1];
    const float* b_qkv  = (const float*)d_in[2];
    const float* W_proj = (const float*)d_in[3];
    const float* b_proj = (const float*)d_in[4];
    float* out = (float*)d_out;

    float*  gq;   cudaGetSymbolAddress((void**)&gq,   g_q);
    __half* kh;   cudaGetSymbolAddress((void**)&kh,   g_kh);
    __half* vh;   cudaGetSymbolAddress((void**)&vh,   g_vh);
    float*  y;    cudaGetSymbolAddress((void**)&y,    g_y);
    float*  part; cudaGetSymbolAddress((void**)&part, g_part);
    float*  psum; cudaGetSymbolAddress((void**)&psum, g_psum);

    // 1) fused QKV GEMM + pack (324 blocks, double-buffered)
    gemm_qkv_kernel<<<dim3(576 / 64, NV / 128), 256>>>(
        x, W_qkv, b_qkv, gq, kh, vh, NV, 576, DIMC);

    // 2) all-scale NA3D partials, one launch (864 blocks)
    na_partial_all_kernel<<<864, 256>>>(gq, kh, vh, part);

    // 3) combine partials -> y
    na_combine_kernel<<<110592 / 256, 256>>>(part, y);

    // 4) proj GEMM, split-K=4 in ONE launch (72 x 3 x 4 = 864 blocks)
    gemm_splitk_kernel<<<dim3(DIMC / 64, NV / 64, 4), 256>>>(
        y, W_proj, psum, NV, DIMC, DIMC, 3);

    // 5) out = sum(psum[0..3]) + bias
    splitk_reduce4_kernel<<<(NV * DIMC / 4) / 256, 256>>>(psum, b_proj, out);
}

// round 8
// speedup vs baseline: 1.1191x; 1.0254x over previous
#include <cuda_runtime.h>
#include <cuda_fp16.h>

// ---------------------------------------------------------------------------
// Problem constants
// ---------------------------------------------------------------------------
#define Dd 8
#define Hh 24
#define Ww 24
#define NV (Dd * Hh * Ww)     /* 4608 voxels */
#define DIMC 192
#define QPS (2 * NV)          /* queries per scale: 2 heads * 4608 = 9216 */
#define PART_STRIDE 36        /* floats per partial record: 32 acc + l + pad */
#define PART_UNIT (QPS * PART_STRIDE)
#define SCALE_F 0.17677669529663687f  /* 32^-0.5 */

static __device__ __align__(16) float  g_q[6 * NV * 32];         // 3.5 MB packed fp32 Q
static __device__ __align__(16) __half g_kh[6 * NV * 32];        // 1.7 MB packed K fp16 (pre-scaled)
static __device__ __align__(16) __half g_vh[6 * NV * 32];        // 1.7 MB packed V fp16
static __device__ __align__(16) float  g_y[NV * DIMC];           // 3.5 MB
static __device__ __align__(16) float  g_part[6 * PART_UNIT];    // 8.0 MB partials
static __device__ __align__(16) float  g_psum[4 * NV * DIMC];    // 14.2 MB split-K partials

__device__ __forceinline__ int iclamp(int v, int lo, int hi) {
    v = v < lo ? lo : v;
    return v > hi ? hi : v;
}

// ---------------------------------------------------------------------------
// Packed f32x2 helpers (FFMA2 path — 2x FFMA throughput on sm_103a)
// ---------------------------------------------------------------------------
__device__ __forceinline__ unsigned long long pack2(float x, float y) {
    unsigned long long r;
    asm("mov.b64 %0, {%1, %2};" : "=l"(r) : "f"(x), "f"(y));
    return r;
}
__device__ __forceinline__ float2 unpack2(unsigned long long u) {
    float2 r;
    asm("mov.b64 {%0, %1}, %2;" : "=f"(r.x), "=f"(r.y) : "l"(u));
    return r;
}
__device__ __forceinline__ unsigned long long ffma2(
    unsigned long long a, unsigned long long b, unsigned long long c) {
    unsigned long long d;
    asm("fma.rn.f32x2 %0, %1, %2, %3;" : "=l"(d) : "l"(a), "l"(b), "l"(c));
    return d;
}

// ---------------------------------------------------------------------------
// Shared GEMM mainloop body: BM=128, BN=64, BK=16, 256 threads, 8x4 tile,
// double-buffered smem. Computes acc2[4][4] over nkt k-tiles from k0.
// ---------------------------------------------------------------------------
#define GEMM_MAINLOOP(Abase, Bbase, Kd, N, nkt)                                 \
    float4 a0v = *(const float4*)(Abase);                                       \
    float4 a1v = *(const float4*)(Abase + (size_t)64 * (Kd));                   \
    float4 bv  = *(const float4*)(Bbase);                                       \
    As[0][ac * 4 + 0][ar] = a0v.x;  As[0][ac * 4 + 1][ar] = a0v.y;              \
    As[0][ac * 4 + 2][ar] = a0v.z;  As[0][ac * 4 + 3][ar] = a0v.w;              \
    As[0][ac * 4 + 0][ar + 64] = a1v.x;  As[0][ac * 4 + 1][ar + 64] = a1v.y;    \
    As[0][ac * 4 + 2][ar + 64] = a1v.z;  As[0][ac * 4 + 3][ar + 64] = a1v.w;    \
    *(float4*)&Bs[0][br][bc * 4] = bv;                                          \
    __syncthreads();                                                            \
    int buf = 0;                                                                \
    for (int t = 0; t < (nkt); t++) {                                           \
        const bool more = (t + 1 < (nkt));                                      \
        if (more) {                                                             \
            const int kq = (t + 1) * 16;                                        \
            a0v = *(const float4*)(Abase + kq);                                 \
            a1v = *(const float4*)(Abase + (size_t)64 * (Kd) + kq);             \
            bv  = *(const float4*)(Bbase + (size_t)kq * (N));                   \
        }                                                                       \
        _Pragma("unroll")                                                       \
        for (int k = 0; k < 16; k++) {                                          \
            const ulonglong2* Ap = (const ulonglong2*)&As[buf][k][ty * 8];      \
            ulonglong2 a01 = Ap[0];                                             \
            ulonglong2 a23 = Ap[1];                                             \
            float4 b4 = *(const float4*)&Bs[buf][k][tx * 4];                    \
            unsigned long long bb0 = pack2(b4.x, b4.x);                         \
            unsigned long long bb1 = pack2(b4.y, b4.y);                         \
            unsigned long long bb2 = pack2(b4.z, b4.z);                         \
            unsigned long long bb3 = pack2(b4.w, b4.w);                         \
            acc2[0][0] = ffma2(a01.x, bb0, acc2[0][0]);                         \
            acc2[0][1] = ffma2(a01.x, bb1, acc2[0][1]);                         \
            acc2[0][2] = ffma2(a01.x, bb2, acc2[0][2]);                         \
            acc2[0][3] = ffma2(a01.x, bb3, acc2[0][3]);                         \
            acc2[1][0] = ffma2(a01.y, bb0, acc2[1][0]);                         \
            acc2[1][1] = ffma2(a01.y, bb1, acc2[1][1]);                         \
            acc2[1][2] = ffma2(a01.y, bb2, acc2[1][2]);                         \
            acc2[1][3] = ffma2(a01.y, bb3, acc2[1][3]);                         \
            acc2[2][0] = ffma2(a23.x, bb0, acc2[2][0]);                         \
            acc2[2][1] = ffma2(a23.x, bb1, acc2[2][1]);                         \
            acc2[2][2] = ffma2(a23.x, bb2, acc2[2][2]);                         \
            acc2[2][3] = ffma2(a23.x, bb3, acc2[2][3]);                         \
            acc2[3][0] = ffma2(a23.y, bb0, acc2[3][0]);                         \
            acc2[3][1] = ffma2(a23.y, bb1, acc2[3][1]);                         \
            acc2[3][2] = ffma2(a23.y, bb2, acc2[3][2]);                         \
            acc2[3][3] = ffma2(a23.y, bb3, acc2[3][3]);                         \
        }                                                                       \
        if (more) {                                                             \
            const int nb = buf ^ 1;                                             \
            As[nb][ac * 4 + 0][ar] = a0v.x;  As[nb][ac * 4 + 1][ar] = a0v.y;    \
            As[nb][ac * 4 + 2][ar] = a0v.z;  As[nb][ac * 4 + 3][ar] = a0v.w;    \
            As[nb][ac * 4 + 0][ar + 64] = a1v.x;                                \
            As[nb][ac * 4 + 1][ar + 64] = a1v.y;                                \
            As[nb][ac * 4 + 2][ar + 64] = a1v.z;                                \
            As[nb][ac * 4 + 3][ar + 64] = a1v.w;                                \
            *(float4*)&Bs[nb][br][bc * 4] = bv;                                 \
            __syncthreads();                                                    \
            buf = nb;                                                           \
        }                                                                       \
    }

// ---------------------------------------------------------------------------
// GEMM1 (QKV, PACK): packed q/k/v = A[M,K] @ B[K,N] + bias.
// ---------------------------------------------------------------------------
__global__ __launch_bounds__(256) void gemm_qkv_kernel(
    const float* __restrict__ A, const float* __restrict__ B,
    const float* __restrict__ bias,
    float* __restrict__ gq, __half* __restrict__ gkh, __half* __restrict__ gvh,
    int M, int N, int Kd)
{
    __shared__ __align__(16) float As[2][16][132];
    __shared__ __align__(16) float Bs[2][16][64];

    const int tid = threadIdx.x;
    const int tx = tid & 15;
    const int ty = tid >> 4;
    const int row0 = blockIdx.y * 128;
    const int col0 = blockIdx.x * 64;

    const int ar = tid >> 2;
    const int ac = tid & 3;
    const int br = tid >> 4;
    const int bc = tid & 15;

    const float* Abase = A + (size_t)(row0 + ar) * Kd + ac * 4;
    const float* Bbase = B + (size_t)br * N + col0 + bc * 4;

    unsigned long long acc2[4][4];
#pragma unroll
    for (int mp = 0; mp < 4; mp++)
#pragma unroll
        for (int n = 0; n < 4; n++) acc2[mp][n] = 0ull;

    GEMM_MAINLOOP(Abase, Bbase, Kd, N, Kd / 16)

    float4 bias4 = *(const float4*)(bias + col0 + tx * 4);

    const int region = col0 >> 6;        // 0..8
    const int kind   = region % 3;       // 0=q 1=k 2=v
    const int scale  = region / 3;
    const int head   = tx >> 3;
    const int ch     = (tx * 4) & 31;
    const int hg     = scale * 2 + head;

#pragma unroll
    for (int mp = 0; mp < 4; mp++) {
        float2 f0 = unpack2(acc2[mp][0]);
        float2 f1 = unpack2(acc2[mp][1]);
        float2 f2 = unpack2(acc2[mp][2]);
        float2 f3 = unpack2(acc2[mp][3]);
        float4 lo = make_float4(f0.x + bias4.x, f1.x + bias4.y,
                                f2.x + bias4.z, f3.x + bias4.w);
        float4 hi = make_float4(f0.y + bias4.x, f1.y + bias4.y,
                                f2.y + bias4.z, f3.y + bias4.w);
        const int r_lo = row0 + ty * 8 + 2 * mp;
        if (kind == 0) {
            *(float4*)(gq + ((size_t)hg * NV + r_lo) * 32 + ch) = lo;
            *(float4*)(gq + ((size_t)hg * NV + r_lo + 1) * 32 + ch) = hi;
        } else {
            float sc = (kind == 1) ? SCALE_F : 1.0f;
            __half* base = (kind == 1) ? gkh : gvh;
            __half2 l01 = __floats2half2_rn(lo.x * sc, lo.y * sc);
            __half2 l23 = __floats2half2_rn(lo.z * sc, lo.w * sc);
            __half2 h01 = __floats2half2_rn(hi.x * sc, hi.y * sc);
            __half2 h23 = __floats2half2_rn(hi.z * sc, hi.w * sc);
            uint2 ul = make_uint2(*(unsigned*)&l01, *(unsigned*)&l23);
            uint2 uh = make_uint2(*(unsigned*)&h01, *(unsigned*)&h23);
            *(uint2*)(base + ((size_t)hg * NV + r_lo) * 32 + ch) = ul;
            *(uint2*)(base + ((size_t)hg * NV + r_lo + 1) * 32 + ch) = uh;
        }
    }
}

// ---------------------------------------------------------------------------
// GEMM2 (proj), split-K=4: psum[z] = A[M, z*48:(z+1)*48] @ B[z-range, N].
// BM=128, BN=64 (8x4 tile halves LDS traffic per FFMA2 vs 4x4).
// Grid (N/64=3, M/128=36, 4) = 432 blocks, ~3 resident/SM, single wave.
// ---------------------------------------------------------------------------
__global__ __launch_bounds__(256) void gemm_splitk_kernel(
    const float* __restrict__ A, const float* __restrict__ B,
    float* __restrict__ psum, int M, int N, int Kd, int nkt)
{
    __shared__ __align__(16) float As[2][16][132];
    __shared__ __align__(16) float Bs[2][16][64];

    const int tid = threadIdx.x;
    const int tx = tid & 15;
    const int ty = tid >> 4;
    const int row0 = blockIdx.y * 128;
    const int col0 = blockIdx.x * 64;
    const int k0   = blockIdx.z * nkt * 16;

    const int ar = tid >> 2;
    const int ac = tid & 3;
    const int br = tid >> 4;
    const int bc = tid & 15;

    const float* Abase = A + (size_t)(row0 + ar) * Kd + k0 + ac * 4;
    const float* Bbase = B + (size_t)(k0 + br) * N + col0 + bc * 4;

    unsigned long long acc2[4][4];
#pragma unroll
    for (int mp = 0; mp < 4; mp++)
#pragma unroll
        for (int n = 0; n < 4; n++) acc2[mp][n] = 0ull;

    GEMM_MAINLOOP(Abase, Bbase, Kd, N, nkt)

    float* out = psum + (size_t)blockIdx.z * M * N;
#pragma unroll
    for (int mp = 0; mp < 4; mp++) {
        float2 f0 = unpack2(acc2[mp][0]);
        float2 f1 = unpack2(acc2[mp][1]);
        float2 f2 = unpack2(acc2[mp][2]);
        float2 f3 = unpack2(acc2[mp][3]);
        const int r_lo = row0 + ty * 8 + 2 * mp;
        *(float4*)(out + (size_t)r_lo * N + col0 + tx * 4) =
            make_float4(f0.x, f1.x, f2.x, f3.x);
        *(float4*)(out + (size_t)(r_lo + 1) * N + col0 + tx * 4) =
            make_float4(f0.y, f1.y, f2.y, f3.y);
    }
}

// Split-K reduction: out = p0+p1+p2+p3 + bias. NV*DIMC/4 float4 threads.
__global__ __launch_bounds__(256) void splitk_reduce4_kernel(
    const float* __restrict__ psum, const float* __restrict__ bias,
    float* __restrict__ out)
{
    const int i = (blockIdx.x * 256 + threadIdx.x) * 4;
    const size_t stride = (size_t)NV * DIMC;
    float4 a = *(const float4*)(psum + i);
    float4 b = *(const float4*)(psum + stride + i);
    float4 c = *(const float4*)(psum + 2 * stride + i);
    float4 d = *(const float4*)(psum + 3 * stride + i);
    float4 bi = *(const float4*)(bias + (i % DIMC));
    *(float4*)(out + i) = make_float4(a.x + b.x + c.x + d.x + bi.x,
                                      a.y + b.y + c.y + d.y + bi.y,
                                      a.z + b.z + c.z + d.z + bi.z,
                                      a.w + b.w + c.w + d.w + bi.w);
}

// ---------------------------------------------------------------------------
// NA3D partial-attention over a depth-slice range [d0off, d0off+ncnt).
// 4-lane query split; HFMA2 math; per-row half2 accum flushed to fp32.
// ---------------------------------------------------------------------------
template <int K>
__device__ __forceinline__ void na_body(
    const float* __restrict__ gq,
    const __half* __restrict__ kh, const __half* __restrict__ vh,
    float* __restrict__ part, int hgbase, int bidx, int d0off, int ncnt)
{
    const int g = bidx * 256 + threadIdx.x;
    const int t = g & 3;
    int r = g >> 2;
    const int w = r % 24; r /= 24;
    const int h = r % 24; r /= 24;
    const int d = r & 7;
    const int head = r >> 3;

    const int start_d = iclamp(d - K / 2, 0, Dd - K);
    const int start_h = iclamp(h - K / 2, 0, Hh - K);
    const int start_w = iclamp(w - K / 2, 0, Ww - K);

    const int hg = hgbase + head;
    const int qrow = (d * Hh + h) * Ww + w;

    const float* qp = gq + ((size_t)hg * NV + qrow) * 32 + t * 8;
    float4 q0 = *(const float4*)qp;
    float4 q1 = *(const float4*)(qp + 4);
    __half2 qh[4];
    qh[0] = __floats2half2_rn(q0.x, q0.y);
    qh[1] = __floats2half2_rn(q0.z, q0.w);
    qh[2] = __floats2half2_rn(q1.x, q1.y);
    qh[3] = __floats2half2_rn(q1.z, q1.w);

    const __half* kbase = kh + (size_t)hg * NV * 32 + t * 8;
    const __half* vbase = vh + (size_t)hg * NV * 32 + t * 8;

    float l = 0.f;
    float fa[8];
#pragma unroll
    for (int i = 0; i < 8; i++) fa[i] = 0.f;

    for (int ddi = 0; ddi < ncnt; ddi++) {
        const int dd = start_d + d0off + ddi;
        for (int hh = 0; hh < K; hh++) {
            const int rowbase = (dd * Hh + start_h + hh) * Ww + start_w;
            __half2 a2[4];
            a2[0] = a2[1] = a2[2] = a2[3] = __floats2half2_rn(0.f, 0.f);
#pragma unroll
            for (int ww = 0; ww < K; ww++) {
                const int row = rowbase + ww;
                const uint4 k4 = *(const uint4*)(kbase + (size_t)row * 32);
                __half2 s2 = __hmul2(qh[0], *(const __half2*)&k4.x);
                s2 = __hfma2(qh[1], *(const __half2*)&k4.y, s2);
                s2 = __hfma2(qh[2], *(const __half2*)&k4.z, s2);
                s2 = __hfma2(qh[3], *(const __half2*)&k4.w, s2);
                float2 sf = __half22float2(s2);
                float s = sf.x + sf.y;
                s += __shfl_xor_sync(0xffffffffu, s, 1);
                s += __shfl_xor_sync(0xffffffffu, s, 2);

                float p = __expf(s);
                l += p;
                __half2 pp = __half2half2(__float2half_rn(p));
                const uint4 v4 = *(const uint4*)(vbase + (size_t)row * 32);
                a2[0] = __hfma2(pp, *(const __half2*)&v4.x, a2[0]);
                a2[1] = __hfma2(pp, *(const __half2*)&v4.y, a2[1]);
                a2[2] = __hfma2(pp, *(const __half2*)&v4.z, a2[2]);
                a2[3] = __hfma2(pp, *(const __half2*)&v4.w, a2[3]);
            }
#pragma unroll
            for (int j = 0; j < 4; j++) {
                float2 fj = __half22float2(a2[j]);
                fa[2 * j]     += fj.x;
                fa[2 * j + 1] += fj.y;
            }
        }
    }

    const int qidx = ((head * Dd + d) * Hh + h) * Ww + w;
    float* pb = part + (size_t)qidx * PART_STRIDE;
    *(float4*)(pb + t * 8)     = make_float4(fa[0], fa[1], fa[2], fa[3]);
    *(float4*)(pb + t * 8 + 4) = make_float4(fa[4], fa[5], fa[6], fa[7]);
    if (t == 0) pb[32] = l;
}

__global__ __launch_bounds__(256) void na_partial_all_kernel(
    const float* __restrict__ gq,
    const __half* __restrict__ kh, const __half* __restrict__ vh,
    float* __restrict__ part)
{
    const int b = blockIdx.x;
    if (b < 144)       na_body<7>(gq, kh, vh, part + 3 * (size_t)PART_UNIT, 4, b,       0, 3);
    else if (b < 288)  na_body<7>(gq, kh, vh, part + 4 * (size_t)PART_UNIT, 4, b - 144, 3, 2);
    else if (b < 432)  na_body<7>(gq, kh, vh, part + 5 * (size_t)PART_UNIT, 4, b - 288, 5, 2);
    else if (b < 576)  na_body<5>(gq, kh, vh, part + 1 * (size_t)PART_UNIT, 2, b - 432, 0, 3);
    else if (b < 720)  na_body<5>(gq, kh, vh, part + 2 * (size_t)PART_UNIT, 2, b - 576, 3, 2);
    else               na_body<3>(gq, kh, vh, part + 0 * (size_t)PART_UNIT, 0, b - 720, 0, 3);
}

// ---------------------------------------------------------------------------
// Combine partials (plain sums) across chunks -> g_y. 110592 threads.
// ---------------------------------------------------------------------------
__global__ __launch_bounds__(256) void na_combine_kernel(
    const float* __restrict__ part, float* __restrict__ y)
{
    const int g = blockIdx.x * 256 + threadIdx.x;
    const int t = g & 3;
    int r = g >> 2;
    const int w = r % 24; r /= 24;
    const int h = r % 24; r /= 24;
    const int d = r & 7;  r >>= 3;
    const int head = r & 1;
    const int s = r >> 1;

    const int cnt = s + 1;
    const size_t base = (size_t)PART_UNIT * (size_t)(s * (s + 1) / 2);
    const int qidx = ((head * Dd + d) * Hh + h) * Ww + w;

    float L = 0.f;
    float o[8];
#pragma unroll
    for (int i = 0; i < 8; i++) o[i] = 0.f;
    for (int c = 0; c < cnt; c++) {
        const float* pb = part + base + (size_t)c * PART_UNIT
                        + (size_t)qidx * PART_STRIDE;
        L += pb[32];
        float4 a0 = *(const float4*)(pb + t * 8);
        float4 a1 = *(const float4*)(pb + t * 8 + 4);
        o[0] += a0.x; o[1] += a0.y; o[2] += a0.z; o[3] += a0.w;
        o[4] += a1.x; o[5] += a1.y; o[6] += a1.z; o[7] += a1.w;
    }
    float inv = 1.f / L;
    const int vr = (d * Hh + h) * Ww + w;
    float* yp = y + (size_t)vr * DIMC + s * 64 + head * 32 + t * 8;
    *(float4*)yp       = make_float4(o[0] * inv, o[1] * inv, o[2] * inv, o[3] * inv);
    *(float4*)(yp + 4) = make_float4(o[4] * inv, o[5] * inv, o[6] * inv, o[7] * inv);
}

// ---------------------------------------------------------------------------
// Launch
// ---------------------------------------------------------------------------
extern "C" void kernel_launch(void* const* d_in, const int* in_sizes, int n_in,
                              void* d_out, int out_size)
{
    (void)in_sizes; (void)n_in; (void)out_size;
    const float* x      = (const float*)d_in[0];
    const float* W_qkv  = (const float*)d_in[1];
    const float* b_qkv  = (const float*)d_in[2];
    const float* W_proj = (const float*)d_in[3];
    const float* b_proj = (const float*)d_in[4];
    float* out = (float*)d_out;

    float*  gq;   cudaGetSymbolAddress((void**)&gq,   g_q);
    __half* kh;   cudaGetSymbolAddress((void**)&kh,   g_kh);
    __half* vh;   cudaGetSymbolAddress((void**)&vh,   g_vh);
    float*  y;    cudaGetSymbolAddress((void**)&y,    g_y);
    float*  part; cudaGetSymbolAddress((void**)&part, g_part);
    float*  psum; cudaGetSymbolAddress((void**)&psum, g_psum);

    // 1) fused QKV GEMM + pack (324 blocks, double-buffered)
    gemm_qkv_kernel<<<dim3(576 / 64, NV / 128), 256>>>(
        x, W_qkv, b_qkv, gq, kh, vh, NV, 576, DIMC);

    // 2) all-scale NA3D partials, one launch (864 blocks)
    na_partial_all_kernel<<<864, 256>>>(gq, kh, vh, part);

    // 3) combine partials -> y
    na_combine_kernel<<<110592 / 256, 256>>>(part, y);

    // 4) proj GEMM, split-K=4 in ONE launch (3 x 36 x 4 = 432 blocks, BM=128)
    gemm_splitk_kernel<<<dim3(DIMC / 64, NV / 128, 4), 256>>>(
        y, W_proj, psum, NV, DIMC, DIMC, 3);

    // 5) out = sum(psum[0..3]) + bias
    splitk_reduce4_kernel<<<(NV * DIMC / 4) / 256, 256>>>(psum, b_proj, out);
}